// round 11
// baseline (speedup 1.0000x reference)
#include <cuda_runtime.h>
#include <cuda_bf16.h>

// Problem dims: B=1, S=256, N=512, C_M=64, C_Z=128, H=8, C_H=32  (H*C_H = 256)
//
// Pipeline:
//   k_ln_m    : LN(m)                         -> d_mn   [r=s*512+n][64]
//   k_mproj   : d_mn @ [Wm;Wg]^T (K=64)       -> d_V [h][j=n][s*32+e], d_G [r][256] (sigmoid)
//   k_zpath   : LN(z) . Wz[h] + mask bias     -> d_W [h][i*512+j]  (logits)
//   k_softmax : row softmax over j            -> d_W in place
//   k_gemm    : per h: w(512x512) @ V(512x8192) -> d_O [i][s][h*32+e]
//   k_wot     : transpose Wo (64x256 -> 256x64)
//   k_out     : (G*O) @ Wo^T (K=256)          -> out [s][i][64]

// ---------------- scratch (static device globals; no allocation) ----------------
__device__ float d_mn[131072 * 64];          //  33.5 MB  normalized m
__device__ float d_V [8 * 512 * 8192];       // 134.2 MB  [h][j][s*32+e]
__device__ float d_G [131072 * 256];         // 134.2 MB  [r][he]
__device__ float d_W [8 * 512 * 512];        //   8.4 MB  [h][i*512+j]
__device__ float d_O [512 * 256 * 256];      // 134.2 MB  [i][s][h*32+e]
__device__ float d_WoT[256 * 64];            //  64 KB    [k][cm]

__inline__ __device__ float warpSum(float v) {
    #pragma unroll
    for (int o = 16; o > 0; o >>= 1) v += __shfl_xor_sync(0xffffffffu, v, o);
    return v;
}
__inline__ __device__ float warpMax(float v) {
    #pragma unroll
    for (int o = 16; o > 0; o >>= 1) v = fmaxf(v, __shfl_xor_sync(0xffffffffu, v, o));
    return v;
}

// ---------------- kernel 1: LayerNorm(m) ----------------
__global__ void k_ln_m(const float* __restrict__ m,
                       const float* __restrict__ lw, const float* __restrict__ lb)
{
    int tid = threadIdx.x, warp = tid >> 5, lane = tid & 31;
    int r = blockIdx.x * 8 + warp;            // r < 131072
    const float* row = m + (size_t)r * 64;
    float x0 = row[lane];
    float x1 = row[lane + 32];
    float s  = warpSum(x0 + x1);
    float ss = warpSum(x0 * x0 + x1 * x1);
    float mu  = s * (1.0f / 64.0f);
    float var = ss * (1.0f / 64.0f) - mu * mu;
    float rinv = rsqrtf(var + 1e-5f);
    d_mn[(size_t)r * 64 + lane]      = (x0 - mu) * rinv * lw[lane]      + lb[lane];
    d_mn[(size_t)r * 64 + lane + 32] = (x1 - mu) * rinv * lw[lane + 32] + lb[lane + 32];
}

// ---------------- kernel 2: V / G projection GEMM ----------------
// C (131072 x 512) = d_mn (131072 x 64) @ Wcat^T, Wcat = [Wm; Wg] (512 x 64).
// Tile 128x128, K chunks of 32. bx<2 -> V outputs (o in 0..255), bx>=2 -> G.
__global__ void k_mproj(const float* __restrict__ Wm, const float* __restrict__ Wg)
{
    __shared__ float As[128][33];   // [m][k]
    __shared__ float Bs[32][128];   // [k][o]
    int tid = threadIdx.x;
    int tx = tid & 15, ty = tid >> 4;
    int bx = blockIdx.x, by = blockIdx.y;
    bool isV = (bx < 2);

    float acc[8][8] = {};
    for (int kt = 0; kt < 64; kt += 32) {
        // A chunk: 128 x 32
        #pragma unroll
        for (int l = 0; l < 4; l++) {
            int idx = tid * 4 + l * 1024;
            int ar = idx >> 5, ac = idx & 31;
            float4 a4 = *(const float4*)(d_mn + (size_t)(by * 128 + ar) * 64 + kt + ac);
            As[ar][ac] = a4.x; As[ar][ac+1] = a4.y; As[ar][ac+2] = a4.z; As[ar][ac+3] = a4.w;
        }
        // B chunk: Bs[k][o_local] = Wsel[o_global][kt+k]
        {
            int o_local = tid >> 1;
            int k0 = (tid & 1) * 16;
            int o_global = bx * 128 + o_local;
            const float* Wrow = isV ? (Wm + (size_t)o_global * 64)
                                    : (Wg + (size_t)(o_global - 256) * 64);
            #pragma unroll
            for (int i = 0; i < 16; i++) Bs[k0 + i][o_local] = Wrow[kt + k0 + i];
        }
        __syncthreads();
        #pragma unroll
        for (int k = 0; k < 32; k++) {
            float a[8], b[8];
            #pragma unroll
            for (int i = 0; i < 8; i++) a[i] = As[ty * 8 + i][k];
            float4 b0 = *(const float4*)(&Bs[k][tx * 8]);
            float4 b1 = *(const float4*)(&Bs[k][tx * 8 + 4]);
            b[0]=b0.x; b[1]=b0.y; b[2]=b0.z; b[3]=b0.w;
            b[4]=b1.x; b[5]=b1.y; b[6]=b1.z; b[7]=b1.w;
            #pragma unroll
            for (int i = 0; i < 8; i++)
                #pragma unroll
                for (int j = 0; j < 8; j++)
                    acc[i][j] += a[i] * b[j];
        }
        __syncthreads();
    }

    int o_base = bx * 128 + tx * 8;           // 8 consecutive outputs, 8-aligned
    #pragma unroll
    for (int i = 0; i < 8; i++) {
        int r = by * 128 + ty * 8 + i;        // r = s*512 + n
        int s = r >> 9, n = r & 511;
        if (isV) {
            int h = o_base >> 5, e = o_base & 31;   // same h for all 8 (8 | 32)
            size_t base = ((size_t)h * 512 + n) * 8192 + (size_t)s * 32 + e;
            *(float4*)(d_V + base)     = make_float4(acc[i][0], acc[i][1], acc[i][2], acc[i][3]);
            *(float4*)(d_V + base + 4) = make_float4(acc[i][4], acc[i][5], acc[i][6], acc[i][7]);
        } else {
            int og = o_base - 256;
            float4 g0, g1;
            g0.x = 1.0f/(1.0f+expf(-acc[i][0])); g0.y = 1.0f/(1.0f+expf(-acc[i][1]));
            g0.z = 1.0f/(1.0f+expf(-acc[i][2])); g0.w = 1.0f/(1.0f+expf(-acc[i][3]));
            g1.x = 1.0f/(1.0f+expf(-acc[i][4])); g1.y = 1.0f/(1.0f+expf(-acc[i][5]));
            g1.z = 1.0f/(1.0f+expf(-acc[i][6])); g1.w = 1.0f/(1.0f+expf(-acc[i][7]));
            size_t base = (size_t)r * 256 + og;
            *(float4*)(d_G + base)     = g0;
            *(float4*)(d_G + base + 4) = g1;
        }
    }
}

// ---------------- kernel 3: z path -> logits ----------------
__global__ void k_zpath(const float* __restrict__ z, const float* __restrict__ mask,
                        const float* __restrict__ lw, const float* __restrict__ lb,
                        const float* __restrict__ Wz)
{
    __shared__ float sWz[8][128];
    __shared__ float sLw[128], sLb[128];
    int tid = threadIdx.x;
    for (int i = tid; i < 1024; i += 256) sWz[i >> 7][i & 127] = Wz[i];
    if (tid < 128) { sLw[tid] = lw[tid]; sLb[tid] = lb[tid]; }
    __syncthreads();

    int warp = tid >> 5, lane = tid & 31;
    int r = blockIdx.x * 8 + warp;            // r = i*512 + j, r < 262144
    const float4 zx = *(const float4*)(z + (size_t)r * 128 + lane * 4);

    float s  = zx.x + zx.y + zx.z + zx.w;
    float ss = zx.x*zx.x + zx.y*zx.y + zx.z*zx.z + zx.w*zx.w;
    s = warpSum(s); ss = warpSum(ss);
    float mu  = s * (1.0f / 128.0f);
    float var = ss * (1.0f / 128.0f) - mu * mu;
    float rinv = rsqrtf(var + 1e-5f);

    float4 w4 = *(const float4*)(sLw + lane * 4);
    float4 b4 = *(const float4*)(sLb + lane * 4);
    float y0 = (zx.x - mu) * rinv * w4.x + b4.x;
    float y1 = (zx.y - mu) * rinv * w4.y + b4.y;
    float y2 = (zx.z - mu) * rinv * w4.z + b4.z;
    float y3 = (zx.w - mu) * rinv * w4.w + b4.w;

    float bias = (1.0f - mask[r]) * (-1000000.0f);
    #pragma unroll
    for (int h = 0; h < 8; h++) {
        float4 wz = *(const float4*)(&sWz[h][lane * 4]);
        float p = y0*wz.x + y1*wz.y + y2*wz.z + y3*wz.w;
        p = warpSum(p);
        if (lane == 0) d_W[(size_t)h * 262144 + r] = p + bias;
    }
}

// ---------------- kernel 4: in-place softmax over j ----------------
__global__ void k_softmax()
{
    int tid = threadIdx.x, warp = tid >> 5, lane = tid & 31;
    int r = blockIdx.x * 8 + warp;            // r < 4096 (h*512 + i)
    float* p = d_W + (size_t)r * 512;
    float v[16];
    float mx = -1e30f;
    #pragma unroll
    for (int u = 0; u < 16; u++) { v[u] = p[u * 32 + lane]; mx = fmaxf(mx, v[u]); }
    mx = warpMax(mx);
    float s = 0.f;
    #pragma unroll
    for (int u = 0; u < 16; u++) { v[u] = expf(v[u] - mx); s += v[u]; }
    s = warpSum(s);
    float inv = 1.0f / s;
    #pragma unroll
    for (int u = 0; u < 16; u++) p[u * 32 + lane] = v[u] * inv;
}

// ---------------- kernel 5: big GEMM per head ----------------
// C[i, t] = sum_j w[h][i][j] * V[h][j][t],  M=512, N=8192, K=512, t = s*32+e.
__global__ void k_gemm()
{
    __shared__ float As[128][17];
    __shared__ float Bs[16][128];
    int tid = threadIdx.x;
    int tx = tid & 15, ty = tid >> 4;
    int bx = blockIdx.x, by = blockIdx.y, h = blockIdx.z;
    const float* A = d_W + (size_t)h * 262144;   // 512x512 row-major
    const float* B = d_V + (size_t)h * 4194304;  // 512x8192 row-major

    float acc[8][8] = {};
    for (int kt = 0; kt < 512; kt += 16) {
        #pragma unroll
        for (int l = 0; l < 2; l++) {
            int e = tid + l * 256;
            int ar = e >> 2, ac = (e & 3) * 4;
            float4 a4 = *(const float4*)(A + (size_t)(by * 128 + ar) * 512 + kt + ac);
            As[ar][ac] = a4.x; As[ar][ac+1] = a4.y; As[ar][ac+2] = a4.z; As[ar][ac+3] = a4.w;
        }
        #pragma unroll
        for (int l = 0; l < 2; l++) {
            int e = tid + l * 256;
            int br = e >> 5, bc = (e & 31) * 4;
            *(float4*)(&Bs[br][bc]) = *(const float4*)(B + (size_t)(kt + br) * 8192 + bx * 128 + bc);
        }
        __syncthreads();
        #pragma unroll
        for (int k = 0; k < 16; k++) {
            float a[8], b[8];
            #pragma unroll
            for (int i = 0; i < 8; i++) a[i] = As[ty * 8 + i][k];
            float4 b0 = *(const float4*)(&Bs[k][tx * 8]);
            float4 b1 = *(const float4*)(&Bs[k][tx * 8 + 4]);
            b[0]=b0.x; b[1]=b0.y; b[2]=b0.z; b[3]=b0.w;
            b[4]=b1.x; b[5]=b1.y; b[6]=b1.z; b[7]=b1.w;
            #pragma unroll
            for (int i = 0; i < 8; i++)
                #pragma unroll
                for (int j = 0; j < 8; j++)
                    acc[i][j] += a[i] * b[j];
        }
        __syncthreads();
    }
    int tcol = bx * 128 + tx * 8;             // 8-aligned, within one s (8 | 32)
    int s = tcol >> 5, e = tcol & 31;
    #pragma unroll
    for (int i = 0; i < 8; i++) {
        int row = by * 128 + ty * 8 + i;      // i index
        size_t base = (size_t)row * 65536 + (size_t)s * 256 + h * 32 + e;
        *(float4*)(d_O + base)     = make_float4(acc[i][0], acc[i][1], acc[i][2], acc[i][3]);
        *(float4*)(d_O + base + 4) = make_float4(acc[i][4], acc[i][5], acc[i][6], acc[i][7]);
    }
}

// ---------------- kernel 6: transpose Wo ----------------
__global__ void k_wot(const float* __restrict__ Wo)
{
    int idx = blockIdx.x * 256 + threadIdx.x;   // < 16384
    int cm = idx >> 8, k = idx & 255;
    d_WoT[k * 64 + cm] = Wo[idx];
}

// ---------------- kernel 7: gate + output projection GEMM ----------------
// out (131072 x 64) = (G .* Ogath) (131072 x 256) @ WoT (256 x 64)
__global__ void k_out(float* __restrict__ out)
{
    __shared__ float As[64][33];
    __shared__ float Bs[32][64];
    int tid = threadIdx.x;
    int tx = tid & 15, ty = tid >> 4;
    int by = blockIdx.x;

    float acc[4][4] = {};
    for (int kt = 0; kt < 256; kt += 32) {
        #pragma unroll
        for (int l = 0; l < 2; l++) {
            int idx = tid * 4 + l * 1024;       // 2048 elems
            int ar = idx >> 5, ac = idx & 31;
            int r = by * 64 + ar;
            int s = r >> 9, i = r & 511;
            float4 g4 = *(const float4*)(d_G + (size_t)r * 256 + kt + ac);
            float4 o4 = *(const float4*)(d_O + (size_t)i * 65536 + (size_t)s * 256 + kt + ac);
            As[ar][ac]   = g4.x * o4.x;
            As[ar][ac+1] = g4.y * o4.y;
            As[ar][ac+2] = g4.z * o4.z;
            As[ar][ac+3] = g4.w * o4.w;
        }
        #pragma unroll
        for (int l = 0; l < 2; l++) {
            int idx = tid * 4 + l * 1024;       // 2048 elems
            int k = idx >> 6, cm = idx & 63;
            *(float4*)(&Bs[k][cm]) = *(const float4*)(d_WoT + (size_t)(kt + k) * 64 + cm);
        }
        __syncthreads();
        #pragma unroll
        for (int k = 0; k < 32; k++) {
            float a[4], b[4];
            #pragma unroll
            for (int i = 0; i < 4; i++) a[i] = As[ty * 4 + i][k];
            float4 b0 = *(const float4*)(&Bs[k][tx * 4]);
            b[0]=b0.x; b[1]=b0.y; b[2]=b0.z; b[3]=b0.w;
            #pragma unroll
            for (int i = 0; i < 4; i++)
                #pragma unroll
                for (int j = 0; j < 4; j++)
                    acc[i][j] += a[i] * b[j];
        }
        __syncthreads();
    }
    #pragma unroll
    for (int i = 0; i < 4; i++) {
        int r = by * 64 + ty * 4 + i;
        *(float4*)(out + (size_t)r * 64 + tx * 4) =
            make_float4(acc[i][0], acc[i][1], acc[i][2], acc[i][3]);
    }
}

extern "C" void kernel_launch(void* const* d_in, const int* in_sizes, int n_in,
                              void* d_out, int out_size)
{
    // Input binding. Expected element counts:
    //   m=8388608, z=33554432, mask=262144, ln_m_*=64, ln_z_*=128,
    //   W_m=W_g=16384, W_z=1024, W_o=16384
    // Hypothesis A (setup_inputs insertion order): m,z,mask,lmw,lmb,lzw,lzb,Wm,Wg,Wz,Wo
    // Hypothesis B (alphabetical): W_g,W_m,W_o,W_z,ln_m_b,ln_m_w,ln_z_b,ln_z_w,m,mask,z
    const float *m, *z, *mask, *lmw, *lmb, *lzw, *lzb, *Wm, *Wg, *Wz, *Wo;
    if (n_in > 0 && in_sizes[0] == 8388608) {           // insertion order
        m   = (const float*)d_in[0];  z   = (const float*)d_in[1];
        mask= (const float*)d_in[2];
        lmw = (const float*)d_in[3];  lmb = (const float*)d_in[4];
        lzw = (const float*)d_in[5];  lzb = (const float*)d_in[6];
        Wm  = (const float*)d_in[7];  Wg  = (const float*)d_in[8];
        Wz  = (const float*)d_in[9];  Wo  = (const float*)d_in[10];
    } else {                                            // alphabetical order
        Wg  = (const float*)d_in[0];  Wm  = (const float*)d_in[1];
        Wo  = (const float*)d_in[2];  Wz  = (const float*)d_in[3];
        lmb = (const float*)d_in[4];  lmw = (const float*)d_in[5];
        lzb = (const float*)d_in[6];  lzw = (const float*)d_in[7];
        m   = (const float*)d_in[8];  mask= (const float*)d_in[9];
        z   = (const float*)d_in[10];
    }
    float* out = (float*)d_out;

    k_ln_m<<<16384, 256>>>(m, lmw, lmb);                 // 131072 rows
    dim3 gp(4, 1024);
    k_mproj<<<gp, 256>>>(Wm, Wg);                        // 131072 x 512 x 64
    k_zpath<<<32768, 256>>>(z, mask, lzw, lzb, Wz);      // 262144 rows
    k_softmax<<<512, 256>>>();                           // 4096 rows
    dim3 gg(64, 4, 8);
    k_gemm<<<gg, 256>>>();                               // 8 x (512 x 8192 x 512)
    k_wot<<<64, 256>>>(Wo);
    k_out<<<2048, 256>>>(out);                           // 131072 x 64 x 256
}

// round 12
// speedup vs baseline: 1.7422x; 1.7422x over previous
#include <cuda_runtime.h>
#include <cuda_bf16.h>
#include <cstdint>

// Problem dims: B=1, S=256, N=512, C_M=64, C_Z=128, H=8, C_H=32  (H*C_H = 256)
//
// Pipeline:
//   k_ln_m    : LN(m)                         -> d_mn   [r=s*512+n][64]
//   k_mproj   : d_mn @ [Wm;Wg]^T (K=64)       -> d_V [h][j=n][s*32+e] (tf32-rounded), d_G (sigmoid)
//   k_zpath   : LN(z) . Wz[h] + mask bias     -> d_W [h][i*512+j]  (logits)
//   k_softmax : row softmax over j            -> d_W in place (tf32-rounded)
//   k_gemm    : per h: w(512x512) @ V(512x8192) via mma.sync tf32 -> d_O [i][s][h*32+e]
//   k_wot     : transpose Wo
//   k_out     : (G*O) @ Wo^T (K=256)          -> out [s][i][64]

// ---------------- scratch ----------------
__device__ float d_mn[131072 * 64];
__device__ float d_V [8 * 512 * 8192];       // tf32-rounded values
__device__ float d_G [131072 * 256];
__device__ float d_W [8 * 512 * 512];        // tf32-rounded softmax weights
__device__ float d_O [512 * 256 * 256];
__device__ float d_WoT[256 * 64];

__inline__ __device__ float warpSum(float v) {
    #pragma unroll
    for (int o = 16; o > 0; o >>= 1) v += __shfl_xor_sync(0xffffffffu, v, o);
    return v;
}
__inline__ __device__ float warpMax(float v) {
    #pragma unroll
    for (int o = 16; o > 0; o >>= 1) v = fmaxf(v, __shfl_xor_sync(0xffffffffu, v, o));
    return v;
}
__inline__ __device__ float to_tf32(float x) {
    uint32_t u;
    asm("cvt.rna.tf32.f32 %0, %1;" : "=r"(u) : "f"(x));
    return __uint_as_float(u);
}

// ---------------- kernel 1: LayerNorm(m) ----------------
__global__ void k_ln_m(const float* __restrict__ m,
                       const float* __restrict__ lw, const float* __restrict__ lb)
{
    int tid = threadIdx.x, warp = tid >> 5, lane = tid & 31;
    int r = blockIdx.x * 8 + warp;
    const float* row = m + (size_t)r * 64;
    float x0 = row[lane];
    float x1 = row[lane + 32];
    float s  = warpSum(x0 + x1);
    float ss = warpSum(x0 * x0 + x1 * x1);
    float mu  = s * (1.0f / 64.0f);
    float var = ss * (1.0f / 64.0f) - mu * mu;
    float rinv = rsqrtf(var + 1e-5f);
    d_mn[(size_t)r * 64 + lane]      = (x0 - mu) * rinv * lw[lane]      + lb[lane];
    d_mn[(size_t)r * 64 + lane + 32] = (x1 - mu) * rinv * lw[lane + 32] + lb[lane + 32];
}

// ---------------- kernel 2: V / G projection GEMM ----------------
__global__ void k_mproj(const float* __restrict__ Wm, const float* __restrict__ Wg)
{
    __shared__ float As[128][33];
    __shared__ float Bs[32][128];
    int tid = threadIdx.x;
    int tx = tid & 15, ty = tid >> 4;
    int bx = blockIdx.x, by = blockIdx.y;
    bool isV = (bx < 2);

    float acc[8][8] = {};
    for (int kt = 0; kt < 64; kt += 32) {
        #pragma unroll
        for (int l = 0; l < 4; l++) {
            int idx = tid * 4 + l * 1024;
            int ar = idx >> 5, ac = idx & 31;
            float4 a4 = *(const float4*)(d_mn + (size_t)(by * 128 + ar) * 64 + kt + ac);
            As[ar][ac] = a4.x; As[ar][ac+1] = a4.y; As[ar][ac+2] = a4.z; As[ar][ac+3] = a4.w;
        }
        {
            int o_local = tid >> 1;
            int k0 = (tid & 1) * 16;
            int o_global = bx * 128 + o_local;
            const float* Wrow = isV ? (Wm + (size_t)o_global * 64)
                                    : (Wg + (size_t)(o_global - 256) * 64);
            #pragma unroll
            for (int i = 0; i < 16; i++) Bs[k0 + i][o_local] = Wrow[kt + k0 + i];
        }
        __syncthreads();
        #pragma unroll
        for (int k = 0; k < 32; k++) {
            float a[8], b[8];
            #pragma unroll
            for (int i = 0; i < 8; i++) a[i] = As[ty * 8 + i][k];
            float4 b0 = *(const float4*)(&Bs[k][tx * 8]);
            float4 b1 = *(const float4*)(&Bs[k][tx * 8 + 4]);
            b[0]=b0.x; b[1]=b0.y; b[2]=b0.z; b[3]=b0.w;
            b[4]=b1.x; b[5]=b1.y; b[6]=b1.z; b[7]=b1.w;
            #pragma unroll
            for (int i = 0; i < 8; i++)
                #pragma unroll
                for (int j = 0; j < 8; j++)
                    acc[i][j] += a[i] * b[j];
        }
        __syncthreads();
    }

    int o_base = bx * 128 + tx * 8;
    #pragma unroll
    for (int i = 0; i < 8; i++) {
        int r = by * 128 + ty * 8 + i;
        int s = r >> 9, n = r & 511;
        if (isV) {
            int h = o_base >> 5, e = o_base & 31;
            size_t base = ((size_t)h * 512 + n) * 8192 + (size_t)s * 32 + e;
            // round V to tf32 here so the MMA consumes pre-rounded bits
            *(float4*)(d_V + base) = make_float4(to_tf32(acc[i][0]), to_tf32(acc[i][1]),
                                                 to_tf32(acc[i][2]), to_tf32(acc[i][3]));
            *(float4*)(d_V + base + 4) = make_float4(to_tf32(acc[i][4]), to_tf32(acc[i][5]),
                                                     to_tf32(acc[i][6]), to_tf32(acc[i][7]));
        } else {
            int og = o_base - 256;
            float4 g0, g1;
            g0.x = 1.0f/(1.0f+expf(-acc[i][0])); g0.y = 1.0f/(1.0f+expf(-acc[i][1]));
            g0.z = 1.0f/(1.0f+expf(-acc[i][2])); g0.w = 1.0f/(1.0f+expf(-acc[i][3]));
            g1.x = 1.0f/(1.0f+expf(-acc[i][4])); g1.y = 1.0f/(1.0f+expf(-acc[i][5]));
            g1.z = 1.0f/(1.0f+expf(-acc[i][6])); g1.w = 1.0f/(1.0f+expf(-acc[i][7]));
            size_t base = (size_t)r * 256 + og;
            *(float4*)(d_G + base)     = g0;
            *(float4*)(d_G + base + 4) = g1;
        }
    }
}

// ---------------- kernel 3: z path -> logits ----------------
__global__ void k_zpath(const float* __restrict__ z, const float* __restrict__ mask,
                        const float* __restrict__ lw, const float* __restrict__ lb,
                        const float* __restrict__ Wz)
{
    __shared__ float sWz[8][128];
    __shared__ float sLw[128], sLb[128];
    int tid = threadIdx.x;
    for (int i = tid; i < 1024; i += 256) sWz[i >> 7][i & 127] = Wz[i];
    if (tid < 128) { sLw[tid] = lw[tid]; sLb[tid] = lb[tid]; }
    __syncthreads();

    int warp = tid >> 5, lane = tid & 31;
    int r = blockIdx.x * 8 + warp;
    const float4 zx = *(const float4*)(z + (size_t)r * 128 + lane * 4);

    float s  = zx.x + zx.y + zx.z + zx.w;
    float ss = zx.x*zx.x + zx.y*zx.y + zx.z*zx.z + zx.w*zx.w;
    s = warpSum(s); ss = warpSum(ss);
    float mu  = s * (1.0f / 128.0f);
    float var = ss * (1.0f / 128.0f) - mu * mu;
    float rinv = rsqrtf(var + 1e-5f);

    float4 w4 = *(const float4*)(sLw + lane * 4);
    float4 b4 = *(const float4*)(sLb + lane * 4);
    float y0 = (zx.x - mu) * rinv * w4.x + b4.x;
    float y1 = (zx.y - mu) * rinv * w4.y + b4.y;
    float y2 = (zx.z - mu) * rinv * w4.z + b4.z;
    float y3 = (zx.w - mu) * rinv * w4.w + b4.w;

    float bias = (1.0f - mask[r]) * (-1000000.0f);
    #pragma unroll
    for (int h = 0; h < 8; h++) {
        float4 wz = *(const float4*)(&sWz[h][lane * 4]);
        float p = y0*wz.x + y1*wz.y + y2*wz.z + y3*wz.w;
        p = warpSum(p);
        if (lane == 0) d_W[(size_t)h * 262144 + r] = p + bias;
    }
}

// ---------------- kernel 4: in-place softmax (tf32-rounded output) ----------------
__global__ void k_softmax()
{
    int tid = threadIdx.x, warp = tid >> 5, lane = tid & 31;
    int r = blockIdx.x * 8 + warp;
    float* p = d_W + (size_t)r * 512;
    float v[16];
    float mx = -1e30f;
    #pragma unroll
    for (int u = 0; u < 16; u++) { v[u] = p[u * 32 + lane]; mx = fmaxf(mx, v[u]); }
    mx = warpMax(mx);
    float s = 0.f;
    #pragma unroll
    for (int u = 0; u < 16; u++) { v[u] = expf(v[u] - mx); s += v[u]; }
    s = warpSum(s);
    float inv = 1.0f / s;
    #pragma unroll
    for (int u = 0; u < 16; u++) p[u * 32 + lane] = to_tf32(v[u] * inv);
}

// ---------------- kernel 5: big GEMM per head — mma.sync tf32 ----------------
// C[i, t] = sum_j w[h][i][j] * V[h][j][t],  M=512, N=8192, K=512, t = s*32+e.
// Block tile 128x128, K-chunk 32. 8 warps in 2(M) x 4(N); warp tile 64x32
// as 4x4 grid of m16n8k8 tf32 MMAs. Inputs pre-rounded to tf32 by producers.
__global__ void __launch_bounds__(256) k_gemm()
{
    // pads chosen so fragment loads are bank-conflict-free:
    //   A: stride 36 -> bank = 4*gid + tig ; B: stride 136 -> bank = 8*tig + gid
    __shared__ float As[128][36];   // [m][k], 32 ks used
    __shared__ float Bs[32][136];   // [k][n], 128 ns used
    int tid = threadIdx.x;
    int warp = tid >> 5, lane = tid & 31;
    int gid = lane >> 2, tig = lane & 3;
    int warp_m = warp & 1, warp_n = warp >> 1;
    int bx = blockIdx.x, by = blockIdx.y, h = blockIdx.z;
    const float* A = d_W + (size_t)h * 262144;   // 512x512
    const float* B = d_V + (size_t)h * 4194304;  // 512x8192

    float acc[4][4][4] = {};   // [m_tile][n_tile][c0..c3]

    for (int kt = 0; kt < 512; kt += 32) {
        // A tile 128x32 (each row: 8 float4)
        #pragma unroll
        for (int l = 0; l < 4; l++) {
            int e = tid + l * 256;
            int ar = e >> 3, ac = (e & 7) * 4;
            *(float4*)(&As[ar][ac]) =
                *(const float4*)(A + (size_t)(by * 128 + ar) * 512 + kt + ac);
        }
        // B tile 32x128
        #pragma unroll
        for (int l = 0; l < 4; l++) {
            int e = tid + l * 256;
            int br = e >> 5, bc = (e & 31) * 4;
            *(float4*)(&Bs[br][bc]) =
                *(const float4*)(B + (size_t)(kt + br) * 8192 + bx * 128 + bc);
        }
        __syncthreads();

        #pragma unroll
        for (int k0 = 0; k0 < 32; k0 += 8) {
            uint32_t af[4][4], bf[4][2];
            #pragma unroll
            for (int mt = 0; mt < 4; mt++) {
                int r0 = warp_m * 64 + mt * 16 + gid;
                af[mt][0] = __float_as_uint(As[r0    ][k0 + tig]);
                af[mt][1] = __float_as_uint(As[r0 + 8][k0 + tig]);
                af[mt][2] = __float_as_uint(As[r0    ][k0 + tig + 4]);
                af[mt][3] = __float_as_uint(As[r0 + 8][k0 + tig + 4]);
            }
            #pragma unroll
            for (int nt = 0; nt < 4; nt++) {
                int c = warp_n * 32 + nt * 8 + gid;
                bf[nt][0] = __float_as_uint(Bs[k0 + tig    ][c]);
                bf[nt][1] = __float_as_uint(Bs[k0 + tig + 4][c]);
            }
            #pragma unroll
            for (int mt = 0; mt < 4; mt++)
                #pragma unroll
                for (int nt = 0; nt < 4; nt++) {
                    asm volatile(
                        "mma.sync.aligned.m16n8k8.row.col.f32.tf32.tf32.f32 "
                        "{%0,%1,%2,%3}, {%4,%5,%6,%7}, {%8,%9}, {%0,%1,%2,%3};\n"
                        : "+f"(acc[mt][nt][0]), "+f"(acc[mt][nt][1]),
                          "+f"(acc[mt][nt][2]), "+f"(acc[mt][nt][3])
                        : "r"(af[mt][0]), "r"(af[mt][1]), "r"(af[mt][2]), "r"(af[mt][3]),
                          "r"(bf[nt][0]), "r"(bf[nt][1]));
                }
        }
        __syncthreads();
    }

    // epilogue: C row = i, col t -> d_O[i][s=t>>5][h*32 + (t&31)]
    #pragma unroll
    for (int mt = 0; mt < 4; mt++) {
        int r0 = by * 128 + warp_m * 64 + mt * 16 + gid;
        #pragma unroll
        for (int nt = 0; nt < 4; nt++) {
            int t = bx * 128 + warp_n * 32 + nt * 8 + 2 * tig;
            int s = t >> 5, e = t & 31;
            size_t b0 = (size_t)r0 * 65536 + (size_t)s * 256 + h * 32 + e;
            size_t b1 = (size_t)(r0 + 8) * 65536 + (size_t)s * 256 + h * 32 + e;
            *(float2*)(d_O + b0) = make_float2(acc[mt][nt][0], acc[mt][nt][1]);
            *(float2*)(d_O + b1) = make_float2(acc[mt][nt][2], acc[mt][nt][3]);
        }
    }
}

// ---------------- kernel 6: transpose Wo ----------------
__global__ void k_wot(const float* __restrict__ Wo)
{
    int idx = blockIdx.x * 256 + threadIdx.x;
    int cm = idx >> 8, k = idx & 255;
    d_WoT[k * 64 + cm] = Wo[idx];
}

// ---------------- kernel 7: gate + output projection GEMM ----------------
__global__ void k_out(float* __restrict__ out)
{
    __shared__ float As[64][33];
    __shared__ float Bs[32][64];
    int tid = threadIdx.x;
    int tx = tid & 15, ty = tid >> 4;
    int by = blockIdx.x;

    float acc[4][4] = {};
    for (int kt = 0; kt < 256; kt += 32) {
        #pragma unroll
        for (int l = 0; l < 2; l++) {
            int idx = tid * 4 + l * 1024;
            int ar = idx >> 5, ac = idx & 31;
            int r = by * 64 + ar;
            int s = r >> 9, i = r & 511;
            float4 g4 = *(const float4*)(d_G + (size_t)r * 256 + kt + ac);
            float4 o4 = *(const float4*)(d_O + (size_t)i * 65536 + (size_t)s * 256 + kt + ac);
            As[ar][ac]   = g4.x * o4.x;
            As[ar][ac+1] = g4.y * o4.y;
            As[ar][ac+2] = g4.z * o4.z;
            As[ar][ac+3] = g4.w * o4.w;
        }
        #pragma unroll
        for (int l = 0; l < 2; l++) {
            int idx = tid * 4 + l * 1024;
            int k = idx >> 6, cm = idx & 63;
            *(float4*)(&Bs[k][cm]) = *(const float4*)(d_WoT + (size_t)(kt + k) * 64 + cm);
        }
        __syncthreads();
        #pragma unroll
        for (int k = 0; k < 32; k++) {
            float a[4], b[4];
            #pragma unroll
            for (int i = 0; i < 4; i++) a[i] = As[ty * 4 + i][k];
            float4 b0 = *(const float4*)(&Bs[k][tx * 4]);
            b[0]=b0.x; b[1]=b0.y; b[2]=b0.z; b[3]=b0.w;
            #pragma unroll
            for (int i = 0; i < 4; i++)
                #pragma unroll
                for (int j = 0; j < 4; j++)
                    acc[i][j] += a[i] * b[j];
        }
        __syncthreads();
    }
    #pragma unroll
    for (int i = 0; i < 4; i++) {
        int r = by * 64 + ty * 4 + i;
        *(float4*)(out + (size_t)r * 64 + tx * 4) =
            make_float4(acc[i][0], acc[i][1], acc[i][2], acc[i][3]);
    }
}

extern "C" void kernel_launch(void* const* d_in, const int* in_sizes, int n_in,
                              void* d_out, int out_size)
{
    const float *m, *z, *mask, *lmw, *lmb, *lzw, *lzb, *Wm, *Wg, *Wz, *Wo;
    if (n_in > 0 && in_sizes[0] == 8388608) {           // insertion order
        m   = (const float*)d_in[0];  z   = (const float*)d_in[1];
        mask= (const float*)d_in[2];
        lmw = (const float*)d_in[3];  lmb = (const float*)d_in[4];
        lzw = (const float*)d_in[5];  lzb = (const float*)d_in[6];
        Wm  = (const float*)d_in[7];  Wg  = (const float*)d_in[8];
        Wz  = (const float*)d_in[9];  Wo  = (const float*)d_in[10];
    } else {                                            // alphabetical order
        Wg  = (const float*)d_in[0];  Wm  = (const float*)d_in[1];
        Wo  = (const float*)d_in[2];  Wz  = (const float*)d_in[3];
        lmb = (const float*)d_in[4];  lmw = (const float*)d_in[5];
        lzb = (const float*)d_in[6];  lzw = (const float*)d_in[7];
        m   = (const float*)d_in[8];  mask= (const float*)d_in[9];
        z   = (const float*)d_in[10];
    }
    float* out = (float*)d_out;

    k_ln_m<<<16384, 256>>>(m, lmw, lmb);
    dim3 gp(4, 1024);
    k_mproj<<<gp, 256>>>(Wm, Wg);
    k_zpath<<<32768, 256>>>(z, mask, lzw, lzb, Wz);
    k_softmax<<<512, 256>>>();
    dim3 gg(64, 4, 8);
    k_gemm<<<gg, 256>>>();
    k_wot<<<64, 256>>>(Wo);
    k_out<<<2048, 256>>>(out);
}

// round 13
// speedup vs baseline: 2.3063x; 1.3238x over previous
#include <cuda_runtime.h>
#include <cuda_bf16.h>
#include <cstdint>

// Problem dims: B=1, S=256, N=512, C_M=64, C_Z=128, H=8, C_H=32  (H*C_H = 256)
//
// Pipeline (tf32 tensor-core GEMMs throughout):
//   k_ln_m    : LN(m) -> d_mn (tf32-rounded)        [r=s*512+n][64]
//   k_mproj   : tf32 MMA: d_mn @ [Wm;Wg]^T          -> d_V [h][j][s*32+e], d_G [r][256]
//   k_zpath   : LN(z) . Wz[h] + mask bias           -> d_W [h][i*512+j]
//   k_softmax : row softmax, tf32-rounded           -> d_W in place
//   k_gemm    : tf32 MMA, reg-staged pipeline: w @ V -> d_O [i][s][h*32+e]
//   k_out     : tf32 MMA: (G .* O) @ Wo^T           -> out [s][i][64]

// ---------------- scratch ----------------
__device__ float d_mn[131072 * 64];
__device__ float d_V [8 * 512 * 8192];       // tf32-rounded
__device__ float d_G [131072 * 256];
__device__ float d_W [8 * 512 * 512];        // tf32-rounded softmax weights
__device__ float d_O [512 * 256 * 256];

__inline__ __device__ float warpSum(float v) {
    #pragma unroll
    for (int o = 16; o > 0; o >>= 1) v += __shfl_xor_sync(0xffffffffu, v, o);
    return v;
}
__inline__ __device__ float warpMax(float v) {
    #pragma unroll
    for (int o = 16; o > 0; o >>= 1) v = fmaxf(v, __shfl_xor_sync(0xffffffffu, v, o));
    return v;
}
__inline__ __device__ float to_tf32(float x) {
    uint32_t u;
    asm("cvt.rna.tf32.f32 %0, %1;" : "=r"(u) : "f"(x));
    return __uint_as_float(u);
}
#define MMA_TF32(acc, af, bf)                                             \
    asm volatile(                                                         \
        "mma.sync.aligned.m16n8k8.row.col.f32.tf32.tf32.f32 "             \
        "{%0,%1,%2,%3}, {%4,%5,%6,%7}, {%8,%9}, {%0,%1,%2,%3};\n"         \
        : "+f"((acc)[0]), "+f"((acc)[1]), "+f"((acc)[2]), "+f"((acc)[3])  \
        : "r"((af)[0]), "r"((af)[1]), "r"((af)[2]), "r"((af)[3]),         \
          "r"((bf)[0]), "r"((bf)[1]))

// ---------------- kernel 1: LayerNorm(m), tf32-rounded output ----------------
__global__ void k_ln_m(const float* __restrict__ m,
                       const float* __restrict__ lw, const float* __restrict__ lb)
{
    int tid = threadIdx.x, warp = tid >> 5, lane = tid & 31;
    int r = blockIdx.x * 8 + warp;
    const float* row = m + (size_t)r * 64;
    float x0 = row[lane];
    float x1 = row[lane + 32];
    float s  = warpSum(x0 + x1);
    float ss = warpSum(x0 * x0 + x1 * x1);
    float mu  = s * (1.0f / 64.0f);
    float var = ss * (1.0f / 64.0f) - mu * mu;
    float rinv = rsqrtf(var + 1e-5f);
    d_mn[(size_t)r * 64 + lane]      = to_tf32((x0 - mu) * rinv * lw[lane]      + lb[lane]);
    d_mn[(size_t)r * 64 + lane + 32] = to_tf32((x1 - mu) * rinv * lw[lane + 32] + lb[lane + 32]);
}

// ---------------- kernel 2: V / G projection — tf32 MMA ----------------
// C (131072 x 512) = d_mn (131072 x 64) @ Wcat^T; Wcat=[Wm;Wg] rows o, cols c.
// Block tile 128x128, K chunks 32. Warps 2(M)x4(N), warp tile 64x32 (4x4 m16n8k8).
__global__ void __launch_bounds__(256) k_mproj(const float* __restrict__ Wm,
                                               const float* __restrict__ Wg)
{
    __shared__ float As[128][36];
    __shared__ float Bs[32][136];
    int tid = threadIdx.x;
    int warp = tid >> 5, lane = tid & 31;
    int gid = lane >> 2, tig = lane & 3;
    int warp_m = warp & 1, warp_n = warp >> 1;
    int bx = blockIdx.x, by = blockIdx.y;
    bool isV = (bx < 2);

    float acc[4][4][4] = {};
    for (int kt = 0; kt < 64; kt += 32) {
        #pragma unroll
        for (int l = 0; l < 4; l++) {
            int e = tid + l * 256;
            int ar = e >> 3, ac = (e & 7) * 4;
            *(float4*)(&As[ar][ac]) =
                *(const float4*)(d_mn + (size_t)(by * 128 + ar) * 64 + kt + ac);
        }
        {
            int o_local = tid >> 1;
            int k0 = (tid & 1) * 16;
            int o_global = bx * 128 + o_local;
            const float* Wrow = isV ? (Wm + (size_t)o_global * 64)
                                    : (Wg + (size_t)(o_global - 256) * 64);
            #pragma unroll
            for (int i = 0; i < 16; i++) Bs[k0 + i][o_local] = to_tf32(Wrow[kt + k0 + i]);
        }
        __syncthreads();
        #pragma unroll
        for (int k0 = 0; k0 < 32; k0 += 8) {
            uint32_t af[4][4], bf[4][2];
            #pragma unroll
            for (int mt = 0; mt < 4; mt++) {
                int r0 = warp_m * 64 + mt * 16 + gid;
                af[mt][0] = __float_as_uint(As[r0    ][k0 + tig]);
                af[mt][1] = __float_as_uint(As[r0 + 8][k0 + tig]);
                af[mt][2] = __float_as_uint(As[r0    ][k0 + tig + 4]);
                af[mt][3] = __float_as_uint(As[r0 + 8][k0 + tig + 4]);
            }
            #pragma unroll
            for (int nt = 0; nt < 4; nt++) {
                int c = warp_n * 32 + nt * 8 + gid;
                bf[nt][0] = __float_as_uint(Bs[k0 + tig    ][c]);
                bf[nt][1] = __float_as_uint(Bs[k0 + tig + 4][c]);
            }
            #pragma unroll
            for (int mt = 0; mt < 4; mt++)
                #pragma unroll
                for (int nt = 0; nt < 4; nt++)
                    MMA_TF32(acc[mt][nt], af[mt], bf[nt]);
        }
        __syncthreads();
    }

    #pragma unroll
    for (int mt = 0; mt < 4; mt++) {
        int rA = by * 128 + warp_m * 64 + mt * 16 + gid;
        #pragma unroll
        for (int nt = 0; nt < 4; nt++) {
            int o = bx * 128 + warp_n * 32 + nt * 8 + 2 * tig;   // even, pair (o,o+1)
            #pragma unroll
            for (int half = 0; half < 2; half++) {
                int r = rA + half * 8;
                int s = r >> 9, n = r & 511;
                float c0 = acc[mt][nt][2 * half], c1 = acc[mt][nt][2 * half + 1];
                if (isV) {
                    int h = o >> 5, e = o & 31;
                    size_t base = ((size_t)h * 512 + n) * 8192 + (size_t)s * 32 + e;
                    *(float2*)(d_V + base) = make_float2(to_tf32(c0), to_tf32(c1));
                } else {
                    size_t base = (size_t)r * 256 + (o - 256);
                    *(float2*)(d_G + base) =
                        make_float2(1.0f / (1.0f + expf(-c0)), 1.0f / (1.0f + expf(-c1)));
                }
            }
        }
    }
}

// ---------------- kernel 3: z path -> logits ----------------
__global__ void k_zpath(const float* __restrict__ z, const float* __restrict__ mask,
                        const float* __restrict__ lw, const float* __restrict__ lb,
                        const float* __restrict__ Wz)
{
    __shared__ float sWz[8][128];
    __shared__ float sLw[128], sLb[128];
    int tid = threadIdx.x;
    for (int i = tid; i < 1024; i += 256) sWz[i >> 7][i & 127] = Wz[i];
    if (tid < 128) { sLw[tid] = lw[tid]; sLb[tid] = lb[tid]; }
    __syncthreads();

    int warp = tid >> 5, lane = tid & 31;
    int r = blockIdx.x * 8 + warp;
    const float4 zx = *(const float4*)(z + (size_t)r * 128 + lane * 4);

    float s  = zx.x + zx.y + zx.z + zx.w;
    float ss = zx.x*zx.x + zx.y*zx.y + zx.z*zx.z + zx.w*zx.w;
    s = warpSum(s); ss = warpSum(ss);
    float mu  = s * (1.0f / 128.0f);
    float var = ss * (1.0f / 128.0f) - mu * mu;
    float rinv = rsqrtf(var + 1e-5f);

    float4 w4 = *(const float4*)(sLw + lane * 4);
    float4 b4 = *(const float4*)(sLb + lane * 4);
    float y0 = (zx.x - mu) * rinv * w4.x + b4.x;
    float y1 = (zx.y - mu) * rinv * w4.y + b4.y;
    float y2 = (zx.z - mu) * rinv * w4.z + b4.z;
    float y3 = (zx.w - mu) * rinv * w4.w + b4.w;

    float bias = (1.0f - mask[r]) * (-1000000.0f);
    #pragma unroll
    for (int h = 0; h < 8; h++) {
        float4 wz = *(const float4*)(&sWz[h][lane * 4]);
        float p = y0*wz.x + y1*wz.y + y2*wz.z + y3*wz.w;
        p = warpSum(p);
        if (lane == 0) d_W[(size_t)h * 262144 + r] = p + bias;
    }
}

// ---------------- kernel 4: in-place softmax (tf32-rounded) ----------------
__global__ void k_softmax()
{
    int tid = threadIdx.x, warp = tid >> 5, lane = tid & 31;
    int r = blockIdx.x * 8 + warp;
    float* p = d_W + (size_t)r * 512;
    float v[16];
    float mx = -1e30f;
    #pragma unroll
    for (int u = 0; u < 16; u++) { v[u] = p[u * 32 + lane]; mx = fmaxf(mx, v[u]); }
    mx = warpMax(mx);
    float s = 0.f;
    #pragma unroll
    for (int u = 0; u < 16; u++) { v[u] = expf(v[u] - mx); s += v[u]; }
    s = warpSum(s);
    float inv = 1.0f / s;
    #pragma unroll
    for (int u = 0; u < 16; u++) p[u * 32 + lane] = to_tf32(v[u] * inv);
}

// ---------------- kernel 5: big GEMM per head — tf32 MMA, reg-staged ----------------
// C[i, t] = sum_j w[h][i][j] * V[h][j][t],  M=512, N=8192, K=512.
// Register-staged pipeline: global loads for chunk kt+32 issue before the MMA
// loop of chunk kt, hiding DRAM latency behind tensor work.
__global__ void __launch_bounds__(256) k_gemm()
{
    __shared__ float As[128][36];
    __shared__ float Bs[32][136];
    int tid = threadIdx.x;
    int warp = tid >> 5, lane = tid & 31;
    int gid = lane >> 2, tig = lane & 3;
    int warp_m = warp & 1, warp_n = warp >> 1;
    int bx = blockIdx.x, by = blockIdx.y, h = blockIdx.z;
    const float* A = d_W + (size_t)h * 262144;   // 512x512
    const float* B = d_V + (size_t)h * 4194304;  // 512x8192

    float acc[4][4][4] = {};
    float4 ra[4], rb[4];

    // prologue: fetch chunk 0 into registers
    #pragma unroll
    for (int l = 0; l < 4; l++) {
        int e = tid + l * 256;
        ra[l] = *(const float4*)(A + (size_t)(by * 128 + (e >> 3)) * 512 + ((e & 7) * 4));
        rb[l] = *(const float4*)(B + (size_t)(e >> 5) * 8192 + bx * 128 + (e & 31) * 4);
    }

    for (int kt = 0; kt < 512; kt += 32) {
        // commit staged registers to smem
        #pragma unroll
        for (int l = 0; l < 4; l++) {
            int e = tid + l * 256;
            *(float4*)(&As[e >> 3][(e & 7) * 4]) = ra[l];
            *(float4*)(&Bs[e >> 5][(e & 31) * 4]) = rb[l];
        }
        __syncthreads();

        // prefetch next chunk into registers (overlaps with MMA below)
        if (kt + 32 < 512) {
            #pragma unroll
            for (int l = 0; l < 4; l++) {
                int e = tid + l * 256;
                ra[l] = *(const float4*)(A + (size_t)(by * 128 + (e >> 3)) * 512
                                           + kt + 32 + ((e & 7) * 4));
                rb[l] = *(const float4*)(B + (size_t)(kt + 32 + (e >> 5)) * 8192
                                           + bx * 128 + (e & 31) * 4);
            }
        }

        #pragma unroll
        for (int k0 = 0; k0 < 32; k0 += 8) {
            uint32_t af[4][4], bf[4][2];
            #pragma unroll
            for (int mt = 0; mt < 4; mt++) {
                int r0 = warp_m * 64 + mt * 16 + gid;
                af[mt][0] = __float_as_uint(As[r0    ][k0 + tig]);
                af[mt][1] = __float_as_uint(As[r0 + 8][k0 + tig]);
                af[mt][2] = __float_as_uint(As[r0    ][k0 + tig + 4]);
                af[mt][3] = __float_as_uint(As[r0 + 8][k0 + tig + 4]);
            }
            #pragma unroll
            for (int nt = 0; nt < 4; nt++) {
                int c = warp_n * 32 + nt * 8 + gid;
                bf[nt][0] = __float_as_uint(Bs[k0 + tig    ][c]);
                bf[nt][1] = __float_as_uint(Bs[k0 + tig + 4][c]);
            }
            #pragma unroll
            for (int mt = 0; mt < 4; mt++)
                #pragma unroll
                for (int nt = 0; nt < 4; nt++)
                    MMA_TF32(acc[mt][nt], af[mt], bf[nt]);
        }
        __syncthreads();
    }

    #pragma unroll
    for (int mt = 0; mt < 4; mt++) {
        int r0 = by * 128 + warp_m * 64 + mt * 16 + gid;
        #pragma unroll
        for (int nt = 0; nt < 4; nt++) {
            int t = bx * 128 + warp_n * 32 + nt * 8 + 2 * tig;
            int s = t >> 5, e = t & 31;
            size_t b0 = (size_t)r0 * 65536 + (size_t)s * 256 + h * 32 + e;
            size_t b1 = (size_t)(r0 + 8) * 65536 + (size_t)s * 256 + h * 32 + e;
            *(float2*)(d_O + b0) = make_float2(acc[mt][nt][0], acc[mt][nt][1]);
            *(float2*)(d_O + b1) = make_float2(acc[mt][nt][2], acc[mt][nt][3]);
        }
    }
}

// ---------------- kernel 6: gate + output projection — tf32 MMA ----------------
// out (131072 x 64) = tf32(G .* Ogath) (131072 x 256) @ tf32(Wo^T) (256 x 64).
// Block tile 128x64, K chunks 32. Warps 4(M)x2(N), warp tile 32x32 (2x4 m16n8k8).
__global__ void __launch_bounds__(256) k_out(float* __restrict__ out,
                                             const float* __restrict__ Wo)
{
    __shared__ float As[128][36];
    __shared__ float Bs[32][72];
    int tid = threadIdx.x;
    int warp = tid >> 5, lane = tid & 31;
    int gid = lane >> 2, tig = lane & 3;
    int warp_m = warp >> 1, warp_n = warp & 1;
    int by = blockIdx.x;

    float acc[2][4][4] = {};
    for (int kt = 0; kt < 256; kt += 32) {
        // A = tf32(G .* O), 128x32
        #pragma unroll
        for (int l = 0; l < 4; l++) {
            int e = tid + l * 256;
            int ar = e >> 3, ac = (e & 7) * 4;
            int r = by * 128 + ar;
            int s = r >> 9, i = r & 511;
            float4 g4 = *(const float4*)(d_G + (size_t)r * 256 + kt + ac);
            float4 o4 = *(const float4*)(d_O + (size_t)i * 65536 + (size_t)s * 256 + kt + ac);
            As[ar][ac]   = to_tf32(g4.x * o4.x);
            As[ar][ac+1] = to_tf32(g4.y * o4.y);
            As[ar][ac+2] = to_tf32(g4.z * o4.z);
            As[ar][ac+3] = to_tf32(g4.w * o4.w);
        }
        // B[k][cm] = tf32(Wo[cm][kt+k]), 32x64
        {
            int cm = tid >> 2, k0 = (tid & 3) * 8;
            const float* Wrow = Wo + (size_t)cm * 256 + kt + k0;
            #pragma unroll
            for (int i = 0; i < 8; i++) Bs[k0 + i][cm] = to_tf32(Wrow[i]);
        }
        __syncthreads();
        #pragma unroll
        for (int k0 = 0; k0 < 32; k0 += 8) {
            uint32_t af[2][4], bf[4][2];
            #pragma unroll
            for (int mt = 0; mt < 2; mt++) {
                int r0 = warp_m * 32 + mt * 16 + gid;
                af[mt][0] = __float_as_uint(As[r0    ][k0 + tig]);
                af[mt][1] = __float_as_uint(As[r0 + 8][k0 + tig]);
                af[mt][2] = __float_as_uint(As[r0    ][k0 + tig + 4]);
                af[mt][3] = __float_as_uint(As[r0 + 8][k0 + tig + 4]);
            }
            #pragma unroll
            for (int nt = 0; nt < 4; nt++) {
                int c = warp_n * 32 + nt * 8 + gid;
                bf[nt][0] = __float_as_uint(Bs[k0 + tig    ][c]);
                bf[nt][1] = __float_as_uint(Bs[k0 + tig + 4][c]);
            }
            #pragma unroll
            for (int mt = 0; mt < 2; mt++)
                #pragma unroll
                for (int nt = 0; nt < 4; nt++)
                    MMA_TF32(acc[mt][nt], af[mt], bf[nt]);
        }
        __syncthreads();
    }

    #pragma unroll
    for (int mt = 0; mt < 2; mt++) {
        int r0 = by * 128 + warp_m * 32 + mt * 16 + gid;
        #pragma unroll
        for (int nt = 0; nt < 4; nt++) {
            int c = warp_n * 32 + nt * 8 + 2 * tig;
            *(float2*)(out + (size_t)r0 * 64 + c) =
                make_float2(acc[mt][nt][0], acc[mt][nt][1]);
            *(float2*)(out + (size_t)(r0 + 8) * 64 + c) =
                make_float2(acc[mt][nt][2], acc[mt][nt][3]);
        }
    }
}

extern "C" void kernel_launch(void* const* d_in, const int* in_sizes, int n_in,
                              void* d_out, int out_size)
{
    const float *m, *z, *mask, *lmw, *lmb, *lzw, *lzb, *Wm, *Wg, *Wz, *Wo;
    if (n_in > 0 && in_sizes[0] == 8388608) {           // insertion order
        m   = (const float*)d_in[0];  z   = (const float*)d_in[1];
        mask= (const float*)d_in[2];
        lmw = (const float*)d_in[3];  lmb = (const float*)d_in[4];
        lzw = (const float*)d_in[5];  lzb = (const float*)d_in[6];
        Wm  = (const float*)d_in[7];  Wg  = (const float*)d_in[8];
        Wz  = (const float*)d_in[9];  Wo  = (const float*)d_in[10];
    } else {                                            // alphabetical order
        Wg  = (const float*)d_in[0];  Wm  = (const float*)d_in[1];
        Wo  = (const float*)d_in[2];  Wz  = (const float*)d_in[3];
        lmb = (const float*)d_in[4];  lmw = (const float*)d_in[5];
        lzb = (const float*)d_in[6];  lzw = (const float*)d_in[7];
        m   = (const float*)d_in[8];  mask= (const float*)d_in[9];
        z   = (const float*)d_in[10];
    }
    float* out = (float*)d_out;

    k_ln_m<<<16384, 256>>>(m, lmw, lmb);
    dim3 gp(4, 1024);
    k_mproj<<<gp, 256>>>(Wm, Wg);
    k_zpath<<<32768, 256>>>(z, mask, lzw, lzb, Wz);
    k_softmax<<<512, 256>>>();
    dim3 gg(64, 4, 8);
    k_gemm<<<gg, 256>>>();
    k_out<<<1024, 256>>>(out, Wo);
}

// round 14
// speedup vs baseline: 2.3284x; 1.0096x over previous
#include <cuda_runtime.h>
#include <cuda_bf16.h>
#include <cstdint>

// Problem dims: B=1, S=256, N=512, C_M=64, C_Z=128, H=8, C_H=32  (H*C_H = 256)
//
// Pipeline (tf32 tensor-core GEMMs):
//   k_ln_m    : LN(m) -> d_mn (tf32-rounded)        [r=s*512+n][64]
//   k_mproj   : tf32 MMA: d_mn @ [Wm;Wg]^T          -> d_V [h][t][j] (TRANSPOSED), d_G [r][256]
//   k_zpath   : LN(z) . Wz[h] + mask bias           -> d_W [h][i*512+j]
//   k_softmax : row softmax, tf32-rounded           -> d_W in place
//   k_gemm    : tf32 MMA, ping-pong double-buffered smem (1 sync/chunk) -> d_O [i][s][h*32+e]
//   k_out     : tf32 MMA: (G .* O) @ Wo^T           -> out [s][i][64]

// ---------------- scratch ----------------
__device__ float d_mn[131072 * 64];
__device__ float d_V [8 * 8192 * 512];       // [h][t=s*32+e][j]  tf32-rounded  134 MB
__device__ float d_G [131072 * 256];
__device__ float d_W [8 * 512 * 512];        // tf32-rounded softmax weights
__device__ float d_O [512 * 256 * 256];

__inline__ __device__ float warpSum(float v) {
    #pragma unroll
    for (int o = 16; o > 0; o >>= 1) v += __shfl_xor_sync(0xffffffffu, v, o);
    return v;
}
__inline__ __device__ float warpMax(float v) {
    #pragma unroll
    for (int o = 16; o > 0; o >>= 1) v = fmaxf(v, __shfl_xor_sync(0xffffffffu, v, o));
    return v;
}
__inline__ __device__ float to_tf32(float x) {
    uint32_t u;
    asm("cvt.rna.tf32.f32 %0, %1;" : "=r"(u) : "f"(x));
    return __uint_as_float(u);
}
#define MMA_TF32(acc, af, bf)                                             \
    asm volatile(                                                         \
        "mma.sync.aligned.m16n8k8.row.col.f32.tf32.tf32.f32 "             \
        "{%0,%1,%2,%3}, {%4,%5,%6,%7}, {%8,%9}, {%0,%1,%2,%3};\n"         \
        : "+f"((acc)[0]), "+f"((acc)[1]), "+f"((acc)[2]), "+f"((acc)[3])  \
        : "r"((af)[0]), "r"((af)[1]), "r"((af)[2]), "r"((af)[3]),         \
          "r"((bf)[0]), "r"((bf)[1]))

// ---------------- kernel 1: LayerNorm(m), tf32-rounded ----------------
__global__ void k_ln_m(const float* __restrict__ m,
                       const float* __restrict__ lw, const float* __restrict__ lb)
{
    int tid = threadIdx.x, warp = tid >> 5, lane = tid & 31;
    int r = blockIdx.x * 8 + warp;
    const float* row = m + (size_t)r * 64;
    float x0 = row[lane];
    float x1 = row[lane + 32];
    float s  = warpSum(x0 + x1);
    float ss = warpSum(x0 * x0 + x1 * x1);
    float mu  = s * (1.0f / 64.0f);
    float var = ss * (1.0f / 64.0f) - mu * mu;
    float rinv = rsqrtf(var + 1e-5f);
    d_mn[(size_t)r * 64 + lane]      = to_tf32((x0 - mu) * rinv * lw[lane]      + lb[lane]);
    d_mn[(size_t)r * 64 + lane + 32] = to_tf32((x1 - mu) * rinv * lw[lane + 32] + lb[lane + 32]);
}

// ---------------- kernel 2: V / G projection — tf32 MMA ----------------
// C (131072 x 512) = d_mn @ [Wm;Wg]^T. V written TRANSPOSED: d_V[h][s*32+e][n].
__global__ void __launch_bounds__(256) k_mproj(const float* __restrict__ Wm,
                                               const float* __restrict__ Wg)
{
    __shared__ float As[128][36];
    __shared__ float Bs[32][136];
    int tid = threadIdx.x;
    int warp = tid >> 5, lane = tid & 31;
    int gid = lane >> 2, tig = lane & 3;
    int warp_m = warp & 1, warp_n = warp >> 1;
    int bx = blockIdx.x, by = blockIdx.y;
    bool isV = (bx < 2);

    float acc[4][4][4] = {};
    for (int kt = 0; kt < 64; kt += 32) {
        #pragma unroll
        for (int l = 0; l < 4; l++) {
            int e = tid + l * 256;
            int ar = e >> 3, ac = (e & 7) * 4;
            *(float4*)(&As[ar][ac]) =
                *(const float4*)(d_mn + (size_t)(by * 128 + ar) * 64 + kt + ac);
        }
        {
            int o_local = tid >> 1;
            int k0 = (tid & 1) * 16;
            int o_global = bx * 128 + o_local;
            const float* Wrow = isV ? (Wm + (size_t)o_global * 64)
                                    : (Wg + (size_t)(o_global - 256) * 64);
            #pragma unroll
            for (int i = 0; i < 16; i++) Bs[k0 + i][o_local] = to_tf32(Wrow[kt + k0 + i]);
        }
        __syncthreads();
        #pragma unroll
        for (int k0 = 0; k0 < 32; k0 += 8) {
            uint32_t af[4][4], bf[4][2];
            #pragma unroll
            for (int mt = 0; mt < 4; mt++) {
                int r0 = warp_m * 64 + mt * 16 + gid;
                af[mt][0] = __float_as_uint(As[r0    ][k0 + tig]);
                af[mt][1] = __float_as_uint(As[r0 + 8][k0 + tig]);
                af[mt][2] = __float_as_uint(As[r0    ][k0 + tig + 4]);
                af[mt][3] = __float_as_uint(As[r0 + 8][k0 + tig + 4]);
            }
            #pragma unroll
            for (int nt = 0; nt < 4; nt++) {
                int c = warp_n * 32 + nt * 8 + gid;
                bf[nt][0] = __float_as_uint(Bs[k0 + tig    ][c]);
                bf[nt][1] = __float_as_uint(Bs[k0 + tig + 4][c]);
            }
            #pragma unroll
            for (int mt = 0; mt < 4; mt++)
                #pragma unroll
                for (int nt = 0; nt < 4; nt++)
                    MMA_TF32(acc[mt][nt], af[mt], bf[nt]);
        }
        __syncthreads();
    }

    #pragma unroll
    for (int mt = 0; mt < 4; mt++) {
        int rA = by * 128 + warp_m * 64 + mt * 16 + gid;
        #pragma unroll
        for (int nt = 0; nt < 4; nt++) {
            int o = bx * 128 + warp_n * 32 + nt * 8 + 2 * tig;   // even pair (o,o+1)
            #pragma unroll
            for (int half = 0; half < 2; half++) {
                int r = rA + half * 8;
                int s = r >> 9, n = r & 511;
                float c0 = acc[mt][nt][2 * half], c1 = acc[mt][nt][2 * half + 1];
                if (isV) {
                    int h = o >> 5, e = o & 31;
                    size_t t = (size_t)s * 32 + e;     // e even, e+1 same head
                    d_V[((size_t)h * 8192 + t    ) * 512 + n] = to_tf32(c0);
                    d_V[((size_t)h * 8192 + t + 1) * 512 + n] = to_tf32(c1);
                } else {
                    size_t base = (size_t)r * 256 + (o - 256);
                    *(float2*)(d_G + base) =
                        make_float2(1.0f / (1.0f + expf(-c0)), 1.0f / (1.0f + expf(-c1)));
                }
            }
        }
    }
}

// ---------------- kernel 3: z path -> logits ----------------
__global__ void k_zpath(const float* __restrict__ z, const float* __restrict__ mask,
                        const float* __restrict__ lw, const float* __restrict__ lb,
                        const float* __restrict__ Wz)
{
    __shared__ float sWz[8][128];
    __shared__ float sLw[128], sLb[128];
    int tid = threadIdx.x;
    for (int i = tid; i < 1024; i += 256) sWz[i >> 7][i & 127] = Wz[i];
    if (tid < 128) { sLw[tid] = lw[tid]; sLb[tid] = lb[tid]; }
    __syncthreads();

    int warp = tid >> 5, lane = tid & 31;
    int r = blockIdx.x * 8 + warp;
    const float4 zx = *(const float4*)(z + (size_t)r * 128 + lane * 4);

    float s  = zx.x + zx.y + zx.z + zx.w;
    float ss = zx.x*zx.x + zx.y*zx.y + zx.z*zx.z + zx.w*zx.w;
    s = warpSum(s); ss = warpSum(ss);
    float mu  = s * (1.0f / 128.0f);
    float var = ss * (1.0f / 128.0f) - mu * mu;
    float rinv = rsqrtf(var + 1e-5f);

    float4 w4 = *(const float4*)(sLw + lane * 4);
    float4 b4 = *(const float4*)(sLb + lane * 4);
    float y0 = (zx.x - mu) * rinv * w4.x + b4.x;
    float y1 = (zx.y - mu) * rinv * w4.y + b4.y;
    float y2 = (zx.z - mu) * rinv * w4.z + b4.z;
    float y3 = (zx.w - mu) * rinv * w4.w + b4.w;

    float bias = (1.0f - mask[r]) * (-1000000.0f);
    #pragma unroll
    for (int h = 0; h < 8; h++) {
        float4 wz = *(const float4*)(&sWz[h][lane * 4]);
        float p = y0*wz.x + y1*wz.y + y2*wz.z + y3*wz.w;
        p = warpSum(p);
        if (lane == 0) d_W[(size_t)h * 262144 + r] = p + bias;
    }
}

// ---------------- kernel 4: in-place softmax (tf32-rounded) ----------------
__global__ void k_softmax()
{
    int tid = threadIdx.x, warp = tid >> 5, lane = tid & 31;
    int r = blockIdx.x * 8 + warp;
    float* p = d_W + (size_t)r * 512;
    float v[16];
    float mx = -1e30f;
    #pragma unroll
    for (int u = 0; u < 16; u++) { v[u] = p[u * 32 + lane]; mx = fmaxf(mx, v[u]); }
    mx = warpMax(mx);
    float s = 0.f;
    #pragma unroll
    for (int u = 0; u < 16; u++) { v[u] = expf(v[u] - mx); s += v[u]; }
    s = warpSum(s);
    float inv = 1.0f / s;
    #pragma unroll
    for (int u = 0; u < 16; u++) p[u * 32 + lane] = to_tf32(v[u] * inv);
}

// ---------------- kernel 5: big GEMM — ping-pong double-buffered tf32 MMA ----------------
// C[i, t] = sum_j w[h][i][j] * V[j][t].  A = d_W[h] (512x512, [i][j]);
// B = d_V[h] ([t][j], 8192x512) — K is contiguous for BOTH operands.
// Smem: 2 stages x (A 128x36 + B 128x36) = 73.7 KB dynamic. ONE sync per chunk:
// chunk n stores buf p, syncs, prefetches n+1 into regs, MMAs buf p. Overwrite of
// buf p at chunk n+2 is safe: the sync of chunk n+1 happens after every warp's
// MMA over buf p (program order).
__global__ void __launch_bounds__(256) k_gemm()
{
    extern __shared__ float sm[];
    float* Asb = sm;            // [2][128*36]
    float* Bsb = sm + 9216;     // [2][128*36]
    int tid = threadIdx.x;
    int warp = tid >> 5, lane = tid & 31;
    int gid = lane >> 2, tig = lane & 3;
    int warp_m = warp & 1, warp_n = warp >> 1;
    int bx = blockIdx.x, by = blockIdx.y, h = blockIdx.z;
    const float* A  = d_W + (size_t)h * 262144;    // [i][j]
    const float* Bv = d_V + (size_t)h * 4194304;   // [t][j]

    float acc[4][4][4] = {};
    float4 ra[4], rb[4];

    #pragma unroll
    for (int l = 0; l < 4; l++) {
        int e = tid + l * 256;
        int row = e >> 3, kc = (e & 7) * 4;
        ra[l] = *(const float4*)(A  + (size_t)(by * 128 + row) * 512 + kc);
        rb[l] = *(const float4*)(Bv + (size_t)(bx * 128 + row) * 512 + kc);
    }

    for (int kt = 0; kt < 512; kt += 32) {
        float* Ap = Asb + ((kt >> 5) & 1) * 4608;
        float* Bp = Bsb + ((kt >> 5) & 1) * 4608;
        #pragma unroll
        for (int l = 0; l < 4; l++) {
            int e = tid + l * 256;
            int row = e >> 3, kc = (e & 7) * 4;
            *(float4*)(Ap + row * 36 + kc) = ra[l];
            *(float4*)(Bp + row * 36 + kc) = rb[l];
        }
        __syncthreads();
        if (kt + 32 < 512) {
            #pragma unroll
            for (int l = 0; l < 4; l++) {
                int e = tid + l * 256;
                int row = e >> 3, kc = (e & 7) * 4;
                ra[l] = *(const float4*)(A  + (size_t)(by * 128 + row) * 512 + kt + 32 + kc);
                rb[l] = *(const float4*)(Bv + (size_t)(bx * 128 + row) * 512 + kt + 32 + kc);
            }
        }
        #pragma unroll
        for (int k0 = 0; k0 < 32; k0 += 8) {
            uint32_t af[4][4], bf[4][2];
            #pragma unroll
            for (int mt = 0; mt < 4; mt++) {
                int r0 = warp_m * 64 + mt * 16 + gid;
                af[mt][0] = __float_as_uint(Ap[ r0      * 36 + k0 + tig]);
                af[mt][1] = __float_as_uint(Ap[(r0 + 8) * 36 + k0 + tig]);
                af[mt][2] = __float_as_uint(Ap[ r0      * 36 + k0 + tig + 4]);
                af[mt][3] = __float_as_uint(Ap[(r0 + 8) * 36 + k0 + tig + 4]);
            }
            #pragma unroll
            for (int nt = 0; nt < 4; nt++) {
                int c = warp_n * 32 + nt * 8 + gid;
                bf[nt][0] = __float_as_uint(Bp[c * 36 + k0 + tig]);
                bf[nt][1] = __float_as_uint(Bp[c * 36 + k0 + tig + 4]);
            }
            #pragma unroll
            for (int mt = 0; mt < 4; mt++)
                #pragma unroll
                for (int nt = 0; nt < 4; nt++)
                    MMA_TF32(acc[mt][nt], af[mt], bf[nt]);
        }
        // single sync per chunk (next iteration's store targets the other buffer)
    }

    #pragma unroll
    for (int mt = 0; mt < 4; mt++) {
        int r0 = by * 128 + warp_m * 64 + mt * 16 + gid;
        #pragma unroll
        for (int nt = 0; nt < 4; nt++) {
            int t = bx * 128 + warp_n * 32 + nt * 8 + 2 * tig;
            int s = t >> 5, e = t & 31;
            size_t b0 = (size_t)r0 * 65536 + (size_t)s * 256 + h * 32 + e;
            size_t b1 = (size_t)(r0 + 8) * 65536 + (size_t)s * 256 + h * 32 + e;
            *(float2*)(d_O + b0) = make_float2(acc[mt][nt][0], acc[mt][nt][1]);
            *(float2*)(d_O + b1) = make_float2(acc[mt][nt][2], acc[mt][nt][3]);
        }
    }
}

// ---------------- kernel 6: gate + output projection — tf32 MMA ----------------
__global__ void __launch_bounds__(256) k_out(float* __restrict__ out,
                                             const float* __restrict__ Wo)
{
    __shared__ float As[128][36];
    __shared__ float Bs[32][72];
    int tid = threadIdx.x;
    int warp = tid >> 5, lane = tid & 31;
    int gid = lane >> 2, tig = lane & 3;
    int warp_m = warp >> 1, warp_n = warp & 1;
    int by = blockIdx.x;

    float acc[2][4][4] = {};
    for (int kt = 0; kt < 256; kt += 32) {
        #pragma unroll
        for (int l = 0; l < 4; l++) {
            int e = tid + l * 256;
            int ar = e >> 3, ac = (e & 7) * 4;
            int r = by * 128 + ar;
            int s = r >> 9, i = r & 511;
            float4 g4 = *(const float4*)(d_G + (size_t)r * 256 + kt + ac);
            float4 o4 = *(const float4*)(d_O + (size_t)i * 65536 + (size_t)s * 256 + kt + ac);
            As[ar][ac]   = to_tf32(g4.x * o4.x);
            As[ar][ac+1] = to_tf32(g4.y * o4.y);
            As[ar][ac+2] = to_tf32(g4.z * o4.z);
            As[ar][ac+3] = to_tf32(g4.w * o4.w);
        }
        {
            int cm = tid >> 2, k0 = (tid & 3) * 8;
            const float* Wrow = Wo + (size_t)cm * 256 + kt + k0;
            #pragma unroll
            for (int i = 0; i < 8; i++) Bs[k0 + i][cm] = to_tf32(Wrow[i]);
        }
        __syncthreads();
        #pragma unroll
        for (int k0 = 0; k0 < 32; k0 += 8) {
            uint32_t af[2][4], bf[4][2];
            #pragma unroll
            for (int mt = 0; mt < 2; mt++) {
                int r0 = warp_m * 32 + mt * 16 + gid;
                af[mt][0] = __float_as_uint(As[r0    ][k0 + tig]);
                af[mt][1] = __float_as_uint(As[r0 + 8][k0 + tig]);
                af[mt][2] = __float_as_uint(As[r0    ][k0 + tig + 4]);
                af[mt][3] = __float_as_uint(As[r0 + 8][k0 + tig + 4]);
            }
            #pragma unroll
            for (int nt = 0; nt < 4; nt++) {
                int c = warp_n * 32 + nt * 8 + gid;
                bf[nt][0] = __float_as_uint(Bs[k0 + tig    ][c]);
                bf[nt][1] = __float_as_uint(Bs[k0 + tig + 4][c]);
            }
            #pragma unroll
            for (int mt = 0; mt < 2; mt++)
                #pragma unroll
                for (int nt = 0; nt < 4; nt++)
                    MMA_TF32(acc[mt][nt], af[mt], bf[nt]);
        }
        __syncthreads();
    }

    #pragma unroll
    for (int mt = 0; mt < 2; mt++) {
        int r0 = by * 128 + warp_m * 32 + mt * 16 + gid;
        #pragma unroll
        for (int nt = 0; nt < 4; nt++) {
            int c = warp_n * 32 + nt * 8 + 2 * tig;
            *(float2*)(out + (size_t)r0 * 64 + c) =
                make_float2(acc[mt][nt][0], acc[mt][nt][1]);
            *(float2*)(out + (size_t)(r0 + 8) * 64 + c) =
                make_float2(acc[mt][nt][2], acc[mt][nt][3]);
        }
    }
}

extern "C" void kernel_launch(void* const* d_in, const int* in_sizes, int n_in,
                              void* d_out, int out_size)
{
    const float *m, *z, *mask, *lmw, *lmb, *lzw, *lzb, *Wm, *Wg, *Wz, *Wo;
    if (n_in > 0 && in_sizes[0] == 8388608) {           // insertion order
        m   = (const float*)d_in[0];  z   = (const float*)d_in[1];
        mask= (const float*)d_in[2];
        lmw = (const float*)d_in[3];  lmb = (const float*)d_in[4];
        lzw = (const float*)d_in[5];  lzb = (const float*)d_in[6];
        Wm  = (const float*)d_in[7];  Wg  = (const float*)d_in[8];
        Wz  = (const float*)d_in[9];  Wo  = (const float*)d_in[10];
    } else {                                            // alphabetical order
        Wg  = (const float*)d_in[0];  Wm  = (const float*)d_in[1];
        Wo  = (const float*)d_in[2];  Wz  = (const float*)d_in[3];
        lmb = (const float*)d_in[4];  lmw = (const float*)d_in[5];
        lzb = (const float*)d_in[6];  lzw = (const float*)d_in[7];
        m   = (const float*)d_in[8];  mask= (const float*)d_in[9];
        z   = (const float*)d_in[10];
    }
    float* out = (float*)d_out;

    const int GEMM_SMEM = 2 * 9216 * 4;   // 73728 bytes
    cudaFuncSetAttribute(k_gemm, cudaFuncAttributeMaxDynamicSharedMemorySize, GEMM_SMEM);

    k_ln_m<<<16384, 256>>>(m, lmw, lmb);
    dim3 gp(4, 1024);
    k_mproj<<<gp, 256>>>(Wm, Wg);
    k_zpath<<<32768, 256>>>(z, mask, lzw, lzb, Wz);
    k_softmax<<<512, 256>>>();
    dim3 gg(64, 4, 8);
    k_gemm<<<gg, 256, GEMM_SMEM>>>();
    k_out<<<1024, 256>>>(out, Wo);
}